// round 4
// baseline (speedup 1.0000x reference)
#include <cuda_runtime.h>
#include <math.h>

#define NPTS 131072   // B*N
#define NB   65536    // N (points per batch)
#define KNN  32
#define FD   64

typedef unsigned long long u64;

// Scratch (no allocations allowed)
__device__ float g_x1[NPTS * 16];   // 8 MB   lrelu(feat @ Wi^T)
__device__ float g_x2[NPTS * 32];   // 16 MB  [g1 | f1]
__device__ float g_x3[NPTS * 64];   // 32 MB  [g2 | f2]

__device__ __forceinline__ float lrelu(float x) { return fmaxf(x, 0.2f * x); }

// ---- packed f32x2 helpers (sm_103a FFMA2 path) ----
__device__ __forceinline__ u64 fma2(u64 a, u64 b, u64 c) {
    u64 r;
    asm("fma.rn.f32x2 %0, %1, %2, %3;" : "=l"(r) : "l"(a), "l"(b), "l"(c));
    return r;
}
__device__ __forceinline__ u64 pk2(float x, float y) {
    u64 r;
    asm("mov.b64 %0, {%1, %2};" : "=l"(r) : "f"(x), "f"(y));
    return r;
}
__device__ __forceinline__ float2 up2(u64 a) {
    float2 v;
    asm("mov.b64 {%0, %1}, %2;" : "=f"(v.x), "=f"(v.y) : "l"(a));
    return v;
}
#define C06_2 0x3F19999A3F19999AULL   // {0.6f, 0.6f}
#define C04_2 0x3ECCCCCD3ECCCCCDULL   // {0.4f, 0.4f}
#define ABSM  0x7FFFFFFF7FFFFFFFULL

// packed lrelu accumulate: acc += lrelu2(s)  where lrelu(x)=0.6x+0.4|x|
__device__ __forceinline__ u64 lrelu_acc2(u64 s, u64 acc) {
    acc = fma2(s, C06_2, acc);
    acc = fma2(s & ABSM, C04_2, acc);
    return acc;
}

// ---------------------------------------------------------------------------
// K1: x1 = lrelu(features @ w_init^T + b_init)   (NPTS, 16)
// ---------------------------------------------------------------------------
__global__ __launch_bounds__(256) void k_init(
    const float* __restrict__ feat, const float* __restrict__ w,
    const float* __restrict__ b)
{
    __shared__ float4 sf4[256];          // 16 points x 64 feats
    __shared__ float  swt[64 * 16];      // transposed w_init
    __shared__ float  sb[16];
    const float* sf = (const float*)sf4;

    int tid = threadIdx.x;
    int fb  = blockIdx.x * 16;

    const float4* f4 = (const float4*)feat + (size_t)fb * 16;
    sf4[tid] = f4[tid];

#pragma unroll
    for (int e = tid; e < 1024; e += 256) {
        int d = e >> 6, i = e & 63;
        swt[i * 16 + d] = w[e];
    }
    if (tid < 16) sb[tid] = b[tid];
    __syncthreads();

    int p = tid >> 4, d = tid & 15;
    float acc = sb[d];
#pragma unroll
    for (int i = 0; i < 64; i++)
        acc = fmaf(sf[p * 64 + i], swt[i * 16 + d], acc);

    g_x1[(size_t)fb * 16 + tid] = lrelu(acc);
}

// ---------------------------------------------------------------------------
// K2: fused geo-MLPs of lfa1 + lfa2 (shared geometry) + x1 gather-mean.
// One warp per point. Geo staged SoA in SMEM; packed f32x2 over neighbor pairs.
// ---------------------------------------------------------------------------
__global__ __launch_bounds__(256) void k_lfa_geo(
    const float* __restrict__ pts, const int* __restrict__ idx,
    const float* __restrict__ w1, const float* __restrict__ b1,
    const float* __restrict__ w2, const float* __restrict__ b2)
{
    __shared__ __align__(16) float sgx[8][32];
    __shared__ __align__(16) float sgy[8][32];
    __shared__ __align__(16) float sgz[8][32];
    __shared__ __align__(16) float sgd[8][32];
    __shared__ int sidx[8][32];

    int lane = threadIdx.x & 31;
    int wid  = threadIdx.x >> 5;
    int r    = blockIdx.x * 8 + wid;
    int base = (r >= NB) ? NB : 0;       // batch row base

    int ij = idx[(size_t)r * KNN + lane];
    sidx[wid][lane] = ij;

    float cx = pts[(size_t)r * 3 + 0];
    float cy = pts[(size_t)r * 3 + 1];
    float cz = pts[(size_t)r * 3 + 2];

    size_t gr = (size_t)(base + ij) * 3;
    float px = pts[gr + 0], py = pts[gr + 1], pz = pts[gr + 2];

    float rx = cx - px, ry = cy - py, rz = cz - pz;
    float dist = sqrtf(fmaf(rx, rx, fmaf(ry, ry, rz * rz)));
    sgx[wid][lane] = rx;
    sgy[wid][lane] = ry;
    sgz[wid][lane] = rz;
    sgd[wid][lane] = dist;

    // per-lane weight rows, packed {w,w}
    float4 w2r = ((const float4*)w2)[lane];
    u64 w2xx = pk2(w2r.x, w2r.x), w2yy = pk2(w2r.y, w2r.y);
    u64 w2zz = pk2(w2r.z, w2r.z), w2ww = pk2(w2r.w, w2r.w);
    u64 bias2 = pk2(b2[lane], b2[lane]);

    int dlo = lane & 15;
    int h   = lane >> 4;
    float4 w1r = ((const float4*)w1)[dlo];
    u64 w1xx = pk2(w1r.x, w1r.x), w1yy = pk2(w1r.y, w1r.y);
    u64 w1zz = pk2(w1r.z, w1r.z), w1ww = pk2(w1r.w, w1r.w);
    u64 bias1 = pk2(b1[dlo], b1[dlo]);

    __syncwarp();

    u64 ag2 = 0, ag1 = 0;
    float af1 = 0.f;

#pragma unroll
    for (int it = 0; it < 8; it++) {
        int j0 = it * 4;
        // LDS.128 broadcast: two packed neighbor-pairs per component
        ulonglong2 gx = *(const ulonglong2*)&sgx[wid][j0];
        ulonglong2 gy = *(const ulonglong2*)&sgy[wid][j0];
        ulonglong2 gz = *(const ulonglong2*)&sgz[wid][j0];
        ulonglong2 gd = *(const ulonglong2*)&sgd[wid][j0];

        // ---- g2: all 32 lanes (d = lane), both pairs ----
        u64 s0 = fma2(gx.x, w2xx, bias2);
        s0 = fma2(gy.x, w2yy, s0);
        s0 = fma2(gz.x, w2zz, s0);
        s0 = fma2(gd.x, w2ww, s0);
        ag2 = lrelu_acc2(s0, ag2);

        u64 s1 = fma2(gx.y, w2xx, bias2);
        s1 = fma2(gy.y, w2yy, s1);
        s1 = fma2(gz.y, w2zz, s1);
        s1 = fma2(gd.y, w2ww, s1);
        ag2 = lrelu_acc2(s1, ag2);

        // ---- g1: lanes<16 take pair0, lanes>=16 take pair1 (dims dlo) ----
        u64 qx = h ? gx.y : gx.x;
        u64 qy = h ? gy.y : gy.x;
        u64 qz = h ? gz.y : gz.x;
        u64 qd = h ? gd.y : gd.x;
        u64 t = fma2(qx, w1xx, bias1);
        t = fma2(qy, w1yy, t);
        t = fma2(qz, w1zz, t);
        t = fma2(qd, w1ww, t);
        ag1 = lrelu_acc2(t, ag1);

        // ---- f1 gather: lanes<16 rows j0,j0+1; lanes>=16 rows j0+2,j0+3 ----
        int jb = j0 + 2 * h;
        int n0 = sidx[wid][jb];
        int n1 = sidx[wid][jb + 1];
        af1 += g_x1[(size_t)(base + n0) * 16 + dlo];
        af1 += g_x1[(size_t)(base + n1) * 16 + dlo];
    }

    const float inv = 1.0f / 32.0f;

    float2 a2 = up2(ag2);
    g_x3[(size_t)r * 64 + lane] = (a2.x + a2.y) * inv;

    // fold lane-halves for g1 / f1
    u64 ag1o = __shfl_down_sync(0xffffffffu, ag1, 16);
    float af1o = __shfl_down_sync(0xffffffffu, af1, 16);
    if (lane < 16) {
        float2 a1  = up2(ag1);
        float2 a1o = up2(ag1o);
        g_x2[(size_t)r * 32 + lane]      = (a1.x + a1.y + a1o.x + a1o.y) * inv;
        g_x2[(size_t)r * 32 + 16 + lane] = (af1 + af1o) * inv;
    }
}

// ---------------------------------------------------------------------------
// K3a: f2[d] = mean_k x2[nbr_k][d]  (32 dims)  -> g_x3[r][32:64]
// ---------------------------------------------------------------------------
__global__ __launch_bounds__(256) void k_gather2(const int* __restrict__ idx)
{
    __shared__ int sidx[8][32];
    int lane = threadIdx.x & 31;
    int wid  = threadIdx.x >> 5;
    int r    = blockIdx.x * 8 + wid;
    int base = (r >= NB) ? NB : 0;

    sidx[wid][lane] = idx[(size_t)r * KNN + lane];
    __syncwarp();

    float acc = 0.f;
#pragma unroll
    for (int j = 0; j < 32; j++) {
        int nr = sidx[wid][j];
        acc += g_x2[(size_t)(base + nr) * 32 + lane];  // coalesced 128B
    }
    g_x3[(size_t)r * 64 + 32 + lane] = acc * (1.0f / 32.0f);
}

// ---------------------------------------------------------------------------
// K3b: out = lrelu(x3 @ wf^T + bf) + lrelu(feat @ wr^T + br)
// SMEM-staged + packed FFMA2. Block: 256 threads, tile 128 pts x 32 outs
// (grid.y = out-half). Thread tile 4 pts x 4 outs.
// w staged as k2-major u64 pairs (row pad 34 -> 272B stride, 16B-aligned
// rows). Per k4 all lanes hit one 128B span of a row -> conflict-free.
// Inner loop per k4: 4 wLDS + 4 xLDS + 32 FFMA2.
// ---------------------------------------------------------------------------
__global__ __launch_bounds__(256) void k_final(
    const float* __restrict__ feat,
    const float* __restrict__ wf, const float* __restrict__ bf,
    const float* __restrict__ wr, const float* __restrict__ br,
    float* __restrict__ out)
{
    __shared__ float4 sx4[128 * 17];            // 128 pts x 64 f, padded
    __shared__ __align__(16) u64 swp[32 * 34];  // [k2][drow] w-pairs, even pad

    int tid   = threadIdx.x;
    int dhalf = blockIdx.y;                     // 0: outs 0-31, 1: outs 32-63
    int r0    = blockIdx.x * 128;
    int c     = tid & 7;                        // out group: local d = c*4..c*4+3
    int rw    = tid >> 3;                       // 0..31; points p = rw + 32*i
    int dloc  = c * 4;

    u64 acc[4][4];
    float po[4][4];

    // ================ phase A: x3 @ wf^T ================
    {
        const float4* src = (const float4*)g_x3 + (size_t)r0 * 16;
#pragma unroll
        for (int e = tid; e < 2048; e += 256) {
            int p = e >> 4, k4 = e & 15;
            sx4[p * 17 + k4] = src[e];
        }
        // w pairs: warp lanes sweep k2 -> contiguous 256B global reads
#pragma unroll
        for (int e = tid; e < 1024; e += 256) {
            int drow = e >> 5, k2 = e & 31;
            swp[k2 * 34 + drow] =
                *(const u64*)(wf + (size_t)(dhalf * 32 + drow) * 64 + k2 * 2);
        }
    }
    __syncthreads();

#pragma unroll
    for (int i = 0; i < 4; i++)
#pragma unroll
        for (int j = 0; j < 4; j++) acc[i][j] = 0ull;

#pragma unroll
    for (int k4 = 0; k4 < 16; k4++) {
        ulonglong2 wA01 = *(const ulonglong2*)&swp[(2 * k4) * 34 + dloc];
        ulonglong2 wA23 = *(const ulonglong2*)&swp[(2 * k4) * 34 + dloc + 2];
        ulonglong2 wB01 = *(const ulonglong2*)&swp[(2 * k4 + 1) * 34 + dloc];
        ulonglong2 wB23 = *(const ulonglong2*)&swp[(2 * k4 + 1) * 34 + dloc + 2];
#pragma unroll
        for (int i = 0; i < 4; i++) {
            ulonglong2 xv = *(const ulonglong2*)&sx4[(rw + 32 * i) * 17 + k4];
            acc[i][0] = fma2(xv.x, wA01.x, acc[i][0]);
            acc[i][0] = fma2(xv.y, wB01.x, acc[i][0]);
            acc[i][1] = fma2(xv.x, wA01.y, acc[i][1]);
            acc[i][1] = fma2(xv.y, wB01.y, acc[i][1]);
            acc[i][2] = fma2(xv.x, wA23.x, acc[i][2]);
            acc[i][2] = fma2(xv.y, wB23.x, acc[i][2]);
            acc[i][3] = fma2(xv.x, wA23.y, acc[i][3]);
            acc[i][3] = fma2(xv.y, wB23.y, acc[i][3]);
        }
    }

    {
        float4 bv = *(const float4*)(bf + dhalf * 32 + dloc);
#pragma unroll
        for (int i = 0; i < 4; i++)
#pragma unroll
            for (int j = 0; j < 4; j++) {
                float2 v = up2(acc[i][j]);
                po[i][j] = lrelu(v.x + v.y + (&bv.x)[j]);
            }
    }

    __syncthreads();   // done reading phase-A tiles

    // ================ phase B: feat @ wr^T ================
    {
        const float4* src = (const float4*)feat + (size_t)r0 * 16;
#pragma unroll
        for (int e = tid; e < 2048; e += 256) {
            int p = e >> 4, k4 = e & 15;
            sx4[p * 17 + k4] = src[e];
        }
#pragma unroll
        for (int e = tid; e < 1024; e += 256) {
            int drow = e >> 5, k2 = e & 31;
            swp[k2 * 34 + drow] =
                *(const u64*)(wr + (size_t)(dhalf * 32 + drow) * 64 + k2 * 2);
        }
    }
    __syncthreads();

#pragma unroll
    for (int i = 0; i < 4; i++)
#pragma unroll
        for (int j = 0; j < 4; j++) acc[i][j] = 0ull;

#pragma unroll
    for (int k4 = 0; k4 < 16; k4++) {
        ulonglong2 wA01 = *(const ulonglong2*)&swp[(2 * k4) * 34 + dloc];
        ulonglong2 wA23 = *(const ulonglong2*)&swp[(2 * k4) * 34 + dloc + 2];
        ulonglong2 wB01 = *(const ulonglong2*)&swp[(2 * k4 + 1) * 34 + dloc];
        ulonglong2 wB23 = *(const ulonglong2*)&swp[(2 * k4 + 1) * 34 + dloc + 2];
#pragma unroll
        for (int i = 0; i < 4; i++) {
            ulonglong2 xv = *(const ulonglong2*)&sx4[(rw + 32 * i) * 17 + k4];
            acc[i][0] = fma2(xv.x, wA01.x, acc[i][0]);
            acc[i][0] = fma2(xv.y, wB01.x, acc[i][0]);
            acc[i][1] = fma2(xv.x, wA01.y, acc[i][1]);
            acc[i][1] = fma2(xv.y, wB01.y, acc[i][1]);
            acc[i][2] = fma2(xv.x, wA23.x, acc[i][2]);
            acc[i][2] = fma2(xv.y, wB23.x, acc[i][2]);
            acc[i][3] = fma2(xv.x, wA23.y, acc[i][3]);
            acc[i][3] = fma2(xv.y, wB23.y, acc[i][3]);
        }
    }

    // combine + store (float4 per point)
    float4 bv2 = *(const float4*)(br + dhalf * 32 + dloc);
    float4* out4 = (float4*)out;
#pragma unroll
    for (int i = 0; i < 4; i++) {
        int p = rw + 32 * i;
        float4 v;
#pragma unroll
        for (int j = 0; j < 4; j++) {
            float2 w2 = up2(acc[i][j]);
            (&v.x)[j] = po[i][j] + lrelu(w2.x + w2.y + (&bv2.x)[j]);
        }
        out4[(size_t)(r0 + p) * 16 + dhalf * 8 + c] = v;
    }
}

// ---------------------------------------------------------------------------
extern "C" void kernel_launch(void* const* d_in, const int* in_sizes, int n_in,
                              void* d_out, int out_size)
{
    const float* points  = (const float*)d_in[0];
    const float* feats   = (const float*)d_in[1];
    const int*   idx     = (const int*)d_in[2];
    const float* w_init  = (const float*)d_in[3];
    const float* b_init  = (const float*)d_in[4];
    const float* w_lfa1  = (const float*)d_in[5];
    const float* b_lfa1  = (const float*)d_in[6];
    const float* w_lfa2  = (const float*)d_in[7];
    const float* b_lfa2  = (const float*)d_in[8];
    const float* w_final = (const float*)d_in[9];
    const float* b_final = (const float*)d_in[10];
    const float* w_res   = (const float*)d_in[11];
    const float* b_res   = (const float*)d_in[12];
    float* out = (float*)d_out;

    k_init<<<NPTS / 16, 256>>>(feats, w_init, b_init);
    k_lfa_geo<<<NPTS / 8, 256>>>(points, idx, w_lfa1, b_lfa1, w_lfa2, b_lfa2);
    k_gather2<<<NPTS / 8, 256>>>(idx);
    k_final<<<dim3(NPTS / 128, 2), 256>>>(feats, w_final, b_final,
                                          w_res, b_res, out);
}

// round 6
// speedup vs baseline: 1.6691x; 1.6691x over previous
#include <cuda_runtime.h>
#include <math.h>

#define NPTS 131072   // B*N
#define NB   65536    // N (points per batch)
#define KNN  32
#define FD   64

typedef unsigned long long u64;

// Scratch (no allocations allowed)
__device__ float g_x1[NPTS * 16];   // 8 MB   lrelu(feat @ Wi^T)
__device__ float g_x2[NPTS * 32];   // 16 MB  [g1 | f1]
__device__ float g_x3[NPTS * 64];   // 32 MB  [g2 | f2]

// Pre-packed k-pair weights for k_final:
// g_wq[which][dhalf][k2][dloc] = {w[D][2*k2], w[D][2*k2+1]},  D = dhalf*32+dloc
__device__ __align__(16) u64 g_wq[2][2][32][32];

__device__ __forceinline__ float lrelu(float x) { return fmaxf(x, 0.2f * x); }

// ---- packed f32x2 helpers (sm_103a FFMA2 path) ----
__device__ __forceinline__ u64 fma2(u64 a, u64 b, u64 c) {
    u64 r;
    asm("fma.rn.f32x2 %0, %1, %2, %3;" : "=l"(r) : "l"(a), "l"(b), "l"(c));
    return r;
}
__device__ __forceinline__ u64 pk2(float x, float y) {
    u64 r;
    asm("mov.b64 %0, {%1, %2};" : "=l"(r) : "f"(x), "f"(y));
    return r;
}
__device__ __forceinline__ float2 up2(u64 a) {
    float2 v;
    asm("mov.b64 {%0, %1}, %2;" : "=f"(v.x), "=f"(v.y) : "l"(a));
    return v;
}
#define C06_2 0x3F19999A3F19999AULL   // {0.6f, 0.6f}
#define C04_2 0x3ECCCCCD3ECCCCCDULL   // {0.4f, 0.4f}
#define ABSM  0x7FFFFFFF7FFFFFFFULL

// packed lrelu accumulate: acc += lrelu2(s)  where lrelu(x)=0.6x+0.4|x|
__device__ __forceinline__ u64 lrelu_acc2(u64 s, u64 acc) {
    acc = fma2(s, C06_2, acc);
    acc = fma2(s & ABSM, C04_2, acc);
    return acc;
}

// ---------------------------------------------------------------------------
// K0: pack w_final / w_res rows into k-pair u64 chunks (one tiny block).
// ---------------------------------------------------------------------------
__global__ __launch_bounds__(256) void k_packw(
    const float* __restrict__ wf, const float* __restrict__ wr)
{
    int t = threadIdx.x;
    u64* dst = &g_wq[0][0][0][0];
#pragma unroll
    for (int e = t; e < 4096; e += 256) {
        int which = e >> 11;
        int rem   = e & 2047;
        int dh    = rem >> 10;
        int k2    = (rem >> 5) & 31;
        int dloc  = rem & 31;
        const float* src = which ? wr : wf;
        dst[e] = *(const u64*)(src + (size_t)(dh * 32 + dloc) * 64 + k2 * 2);
    }
}

// ---------------------------------------------------------------------------
// K1: x1 = lrelu(features @ w_init^T + b_init)   (NPTS, 16)
// ---------------------------------------------------------------------------
__global__ __launch_bounds__(256) void k_init(
    const float* __restrict__ feat, const float* __restrict__ w,
    const float* __restrict__ b)
{
    __shared__ float4 sf4[256];          // 16 points x 64 feats
    __shared__ float  swt[64 * 16];      // transposed w_init
    __shared__ float  sb[16];
    const float* sf = (const float*)sf4;

    int tid = threadIdx.x;
    int fb  = blockIdx.x * 16;

    const float4* f4 = (const float4*)feat + (size_t)fb * 16;
    sf4[tid] = f4[tid];

#pragma unroll
    for (int e = tid; e < 1024; e += 256) {
        int d = e >> 6, i = e & 63;
        swt[i * 16 + d] = w[e];
    }
    if (tid < 16) sb[tid] = b[tid];
    __syncthreads();

    int p = tid >> 4, d = tid & 15;
    float acc = sb[d];
#pragma unroll
    for (int i = 0; i < 64; i++)
        acc = fmaf(sf[p * 64 + i], swt[i * 16 + d], acc);

    g_x1[(size_t)fb * 16 + tid] = lrelu(acc);
}

// ---------------------------------------------------------------------------
// K2: fused geo-MLPs of lfa1 + lfa2 (shared geometry) + x1 gather-mean.
// One warp per point. Geo staged SoA in SMEM; packed f32x2 over neighbor pairs.
// ---------------------------------------------------------------------------
__global__ __launch_bounds__(256) void k_lfa_geo(
    const float* __restrict__ pts, const int* __restrict__ idx,
    const float* __restrict__ w1, const float* __restrict__ b1,
    const float* __restrict__ w2, const float* __restrict__ b2)
{
    __shared__ __align__(16) float sgx[8][32];
    __shared__ __align__(16) float sgy[8][32];
    __shared__ __align__(16) float sgz[8][32];
    __shared__ __align__(16) float sgd[8][32];
    __shared__ int sidx[8][32];

    int lane = threadIdx.x & 31;
    int wid  = threadIdx.x >> 5;
    int r    = blockIdx.x * 8 + wid;
    int base = (r >= NB) ? NB : 0;       // batch row base

    int ij = idx[(size_t)r * KNN + lane];
    sidx[wid][lane] = ij;

    float cx = pts[(size_t)r * 3 + 0];
    float cy = pts[(size_t)r * 3 + 1];
    float cz = pts[(size_t)r * 3 + 2];

    size_t gr = (size_t)(base + ij) * 3;
    float px = pts[gr + 0], py = pts[gr + 1], pz = pts[gr + 2];

    float rx = cx - px, ry = cy - py, rz = cz - pz;
    float dist = sqrtf(fmaf(rx, rx, fmaf(ry, ry, rz * rz)));
    sgx[wid][lane] = rx;
    sgy[wid][lane] = ry;
    sgz[wid][lane] = rz;
    sgd[wid][lane] = dist;

    // per-lane weight rows, packed {w,w}
    float4 w2r = ((const float4*)w2)[lane];
    u64 w2xx = pk2(w2r.x, w2r.x), w2yy = pk2(w2r.y, w2r.y);
    u64 w2zz = pk2(w2r.z, w2r.z), w2ww = pk2(w2r.w, w2r.w);
    u64 bias2 = pk2(b2[lane], b2[lane]);

    int dlo = lane & 15;
    int h   = lane >> 4;
    float4 w1r = ((const float4*)w1)[dlo];
    u64 w1xx = pk2(w1r.x, w1r.x), w1yy = pk2(w1r.y, w1r.y);
    u64 w1zz = pk2(w1r.z, w1r.z), w1ww = pk2(w1r.w, w1r.w);
    u64 bias1 = pk2(b1[dlo], b1[dlo]);

    __syncwarp();

    u64 ag2 = 0, ag1 = 0;
    float af1 = 0.f;

#pragma unroll
    for (int it = 0; it < 8; it++) {
        int j0 = it * 4;
        // LDS.128 broadcast: two packed neighbor-pairs per component
        ulonglong2 gx = *(const ulonglong2*)&sgx[wid][j0];
        ulonglong2 gy = *(const ulonglong2*)&sgy[wid][j0];
        ulonglong2 gz = *(const ulonglong2*)&sgz[wid][j0];
        ulonglong2 gd = *(const ulonglong2*)&sgd[wid][j0];

        // ---- g2: all 32 lanes (d = lane), both pairs ----
        u64 s0 = fma2(gx.x, w2xx, bias2);
        s0 = fma2(gy.x, w2yy, s0);
        s0 = fma2(gz.x, w2zz, s0);
        s0 = fma2(gd.x, w2ww, s0);
        ag2 = lrelu_acc2(s0, ag2);

        u64 s1 = fma2(gx.y, w2xx, bias2);
        s1 = fma2(gy.y, w2yy, s1);
        s1 = fma2(gz.y, w2zz, s1);
        s1 = fma2(gd.y, w2ww, s1);
        ag2 = lrelu_acc2(s1, ag2);

        // ---- g1: lanes<16 take pair0, lanes>=16 take pair1 (dims dlo) ----
        u64 qx = h ? gx.y : gx.x;
        u64 qy = h ? gy.y : gy.x;
        u64 qz = h ? gz.y : gz.x;
        u64 qd = h ? gd.y : gd.x;
        u64 t = fma2(qx, w1xx, bias1);
        t = fma2(qy, w1yy, t);
        t = fma2(qz, w1zz, t);
        t = fma2(qd, w1ww, t);
        ag1 = lrelu_acc2(t, ag1);

        // ---- f1 gather: lanes<16 rows j0,j0+1; lanes>=16 rows j0+2,j0+3 ----
        int jb = j0 + 2 * h;
        int n0 = sidx[wid][jb];
        int n1 = sidx[wid][jb + 1];
        af1 += g_x1[(size_t)(base + n0) * 16 + dlo];
        af1 += g_x1[(size_t)(base + n1) * 16 + dlo];
    }

    const float inv = 1.0f / 32.0f;

    float2 a2 = up2(ag2);
    g_x3[(size_t)r * 64 + lane] = (a2.x + a2.y) * inv;

    // fold lane-halves for g1 / f1
    u64 ag1o = __shfl_down_sync(0xffffffffu, ag1, 16);
    float af1o = __shfl_down_sync(0xffffffffu, af1, 16);
    if (lane < 16) {
        float2 a1  = up2(ag1);
        float2 a1o = up2(ag1o);
        g_x2[(size_t)r * 32 + lane]      = (a1.x + a1.y + a1o.x + a1o.y) * inv;
        g_x2[(size_t)r * 32 + 16 + lane] = (af1 + af1o) * inv;
    }
}

// ---------------------------------------------------------------------------
// K3a: f2[d] = mean_k x2[nbr_k][d]  (32 dims)  -> g_x3[r][32:64]
// ---------------------------------------------------------------------------
__global__ __launch_bounds__(256) void k_gather2(const int* __restrict__ idx)
{
    __shared__ int sidx[8][32];
    int lane = threadIdx.x & 31;
    int wid  = threadIdx.x >> 5;
    int r    = blockIdx.x * 8 + wid;
    int base = (r >= NB) ? NB : 0;

    sidx[wid][lane] = idx[(size_t)r * KNN + lane];
    __syncwarp();

    float acc = 0.f;
#pragma unroll
    for (int j = 0; j < 32; j++) {
        int nr = sidx[wid][j];
        acc += g_x2[(size_t)(base + nr) * 32 + lane];  // coalesced 128B
    }
    g_x3[(size_t)r * 64 + 32 + lane] = acc * (1.0f / 32.0f);
}

// ---------------------------------------------------------------------------
// K3b: out = lrelu(x3 @ wf^T + bf) + lrelu(feat @ wr^T + br)
// R1 skeleton (128 thr, 8 pts x 4 outs, x staged in SMEM) + packed FFMA2.
// w read via LDG.128 from pre-packed g_wq (L1-resident, coalesced, no SMEM
// crossbar traffic, no packing movs). Per k4: 8 xLDS + 4 wLDG + 64 FFMA2.
// ---------------------------------------------------------------------------
__global__ __launch_bounds__(128) void k_final(
    const float* __restrict__ feat,
    const float* __restrict__ bf, const float* __restrict__ br,
    float* __restrict__ out)
{
    __shared__ float4 sx4[128 * 17];            // 128 pts x 64 f, padded

    int tid   = threadIdx.x;
    int dhalf = blockIdx.y;                     // 0: outs 0-31, 1: outs 32-63
    int r0    = blockIdx.x * 128;
    int c     = tid & 7;                        // out group: local d = c*4..c*4+3
    int rw    = tid >> 3;                       // 0..15; points p = rw + 16*i
    int dloc  = c * 4;

    u64 acc[8][4];
    float po[8][4];

    // ================ phase A: x3 @ wf^T ================
    {
        const float4* src = (const float4*)g_x3 + (size_t)r0 * 16;
#pragma unroll
        for (int e = tid; e < 2048; e += 128) {
            int p = e >> 4, k4 = e & 15;
            sx4[p * 17 + k4] = src[e];
        }
    }
    __syncthreads();

#pragma unroll
    for (int i = 0; i < 8; i++)
#pragma unroll
        for (int j = 0; j < 4; j++) acc[i][j] = 0ull;

#pragma unroll
    for (int k4 = 0; k4 < 16; k4++) {
        // w pairs for k2 = 2k4 (wv0: d+0,d+1; wv1: d+2,d+3) and k2 = 2k4+1
        const ulonglong2* wpA = (const ulonglong2*)&g_wq[0][dhalf][2 * k4][dloc];
        const ulonglong2* wpB = (const ulonglong2*)&g_wq[0][dhalf][2 * k4 + 1][dloc];
        ulonglong2 wv0 = wpA[0], wv1 = wpA[1];
        ulonglong2 wv2 = wpB[0], wv3 = wpB[1];
#pragma unroll
        for (int i = 0; i < 8; i++) {
            ulonglong2 xv = *(const ulonglong2*)&sx4[(rw + 16 * i) * 17 + k4];
            acc[i][0] = fma2(xv.x, wv0.x, acc[i][0]);
            acc[i][0] = fma2(xv.y, wv2.x, acc[i][0]);
            acc[i][1] = fma2(xv.x, wv0.y, acc[i][1]);
            acc[i][1] = fma2(xv.y, wv2.y, acc[i][1]);
            acc[i][2] = fma2(xv.x, wv1.x, acc[i][2]);
            acc[i][2] = fma2(xv.y, wv3.x, acc[i][2]);
            acc[i][3] = fma2(xv.x, wv1.y, acc[i][3]);
            acc[i][3] = fma2(xv.y, wv3.y, acc[i][3]);
        }
    }

    {
        float4 bv = *(const float4*)(bf + dhalf * 32 + dloc);
#pragma unroll
        for (int i = 0; i < 8; i++)
#pragma unroll
            for (int j = 0; j < 4; j++) {
                float2 v = up2(acc[i][j]);
                po[i][j] = lrelu(v.x + v.y + (&bv.x)[j]);
            }
    }

    __syncthreads();   // done reading phase-A tile

    // ================ phase B: feat @ wr^T ================
    {
        const float4* src = (const float4*)feat + (size_t)r0 * 16;
#pragma unroll
        for (int e = tid; e < 2048; e += 128) {
            int p = e >> 4, k4 = e & 15;
            sx4[p * 17 + k4] = src[e];
        }
    }
    __syncthreads();

#pragma unroll
    for (int i = 0; i < 8; i++)
#pragma unroll
        for (int j = 0; j < 4; j++) acc[i][j] = 0ull;

#pragma unroll
    for (int k4 = 0; k4 < 16; k4++) {
        const ulonglong2* wpA = (const ulonglong2*)&g_wq[1][dhalf][2 * k4][dloc];
        const ulonglong2* wpB = (const ulonglong2*)&g_wq[1][dhalf][2 * k4 + 1][dloc];
        ulonglong2 wv0 = wpA[0], wv1 = wpA[1];
        ulonglong2 wv2 = wpB[0], wv3 = wpB[1];
#pragma unroll
        for (int i = 0; i < 8; i++) {
            ulonglong2 xv = *(const ulonglong2*)&sx4[(rw + 16 * i) * 17 + k4];
            acc[i][0] = fma2(xv.x, wv0.x, acc[i][0]);
            acc[i][0] = fma2(xv.y, wv2.x, acc[i][0]);
            acc[i][1] = fma2(xv.x, wv0.y, acc[i][1]);
            acc[i][1] = fma2(xv.y, wv2.y, acc[i][1]);
            acc[i][2] = fma2(xv.x, wv1.x, acc[i][2]);
            acc[i][2] = fma2(xv.y, wv3.x, acc[i][2]);
            acc[i][3] = fma2(xv.x, wv1.y, acc[i][3]);
            acc[i][3] = fma2(xv.y, wv3.y, acc[i][3]);
        }
    }

    // combine + store (float4 per point)
    float4 bv2 = *(const float4*)(br + dhalf * 32 + dloc);
    float4* out4 = (float4*)out;
#pragma unroll
    for (int i = 0; i < 8; i++) {
        int p = rw + 16 * i;
        float4 v;
#pragma unroll
        for (int j = 0; j < 4; j++) {
            float2 w2 = up2(acc[i][j]);
            (&v.x)[j] = po[i][j] + lrelu(w2.x + w2.y + (&bv2.x)[j]);
        }
        out4[(size_t)(r0 + p) * 16 + dhalf * 8 + c] = v;
    }
}

// ---------------------------------------------------------------------------
extern "C" void kernel_launch(void* const* d_in, const int* in_sizes, int n_in,
                              void* d_out, int out_size)
{
    const float* points  = (const float*)d_in[0];
    const float* feats   = (const float*)d_in[1];
    const int*   idx     = (const int*)d_in[2];
    const float* w_init  = (const float*)d_in[3];
    const float* b_init  = (const float*)d_in[4];
    const float* w_lfa1  = (const float*)d_in[5];
    const float* b_lfa1  = (const float*)d_in[6];
    const float* w_lfa2  = (const float*)d_in[7];
    const float* b_lfa2  = (const float*)d_in[8];
    const float* w_final = (const float*)d_in[9];
    const float* b_final = (const float*)d_in[10];
    const float* w_res   = (const float*)d_in[11];
    const float* b_res   = (const float*)d_in[12];
    float* out = (float*)d_out;

    k_packw<<<1, 256>>>(w_final, w_res);
    k_init<<<NPTS / 16, 256>>>(feats, w_init, b_init);
    k_lfa_geo<<<NPTS / 8, 256>>>(points, idx, w_lfa1, b_lfa1, w_lfa2, b_lfa2);
    k_gather2<<<NPTS / 8, 256>>>(idx);
    k_final<<<dim3(NPTS / 128, 2), 128>>>(feats, b_final, b_res, out);
}